// round 6
// baseline (speedup 1.0000x reference)
#include <cuda_runtime.h>

#define BB  8
#define NP  2048
#define CI  64
#define CO  128
#define KK  16

// output layout: [ y (B*CO*N) | knn_mlp_x (B*CO*N*K) | local_coords (B*3*N*K) ]
#define KNN_OFF (BB*CO*NP)                 // 2,097,152
#define LC_OFF  (KNN_OFF + BB*CO*NP*KK)    // 35,651,584

// scratch (no allocations allowed -> device globals)
__device__ int   g_idx[BB*NP*KK];          // 1 MB
__device__ float g_F[BB*NP*CO];            // 8 MB

// ---------------------------------------------------------------------------
// Kernel 1: exact KNN (top-16 smallest d2, stable ties) + local_coords output
// grid (16, 8), block 128. One thread per query point.
// ---------------------------------------------------------------------------
__global__ void __launch_bounds__(128) knn_kernel(const float* __restrict__ coords,
                                                  float* __restrict__ out) {
    __shared__ float4 sp[NP];              // {x, y, z, sq} per candidate, 32 KB
    const int b   = blockIdx.y;
    const int tid = threadIdx.x;
    const float* cb = coords + b * 3 * NP;
    for (int i = tid; i < NP; i += 128) {
        float x = cb[i], y = cb[NP + i], z = cb[2 * NP + i];
        // sq = ((x*x)+(y*y))+(z*z) with explicit rounding (no fma contraction)
        float sq = __fadd_rn(__fadd_rn(__fmul_rn(x, x), __fmul_rn(y, y)),
                             __fmul_rn(z, z));
        sp[i] = make_float4(x, y, z, sq);
    }
    __syncthreads();

    const int n = blockIdx.x * 128 + tid;
    const float4 q = sp[n];
    const float qs = q.w;

    float bd[KK];
    int   bi[KK];
#pragma unroll
    for (int k = 0; k < KK; k++) { bd[k] = 3.402823466e38f; bi[k] = 0; }
    float thr = 3.402823466e38f;

#pragma unroll 4
    for (int j = 0; j < NP; j++) {
        float4 p = sp[j];
        // dot = fma(z,z', fma(y,y', x*x'))  (k-ascending fp32 fma chain)
        float dot = __fmaf_rn(q.z, p.z, __fmaf_rn(q.y, p.y, __fmul_rn(q.x, p.x)));
        // d2 = (sq_n + sq_m) - 2*dot
        float d = __fsub_rn(__fadd_rn(qs, p.w), __fmul_rn(2.0f, dot));
        if (d < thr) {                      // strict: equal keeps earlier index
            int pos = KK - 1;
            while (pos > 0 && bd[pos - 1] > d) {   // stable shift
                bd[pos] = bd[pos - 1]; bi[pos] = bi[pos - 1]; pos--;
            }
            bd[pos] = d; bi[pos] = j;
            thr = bd[KK - 1];
        }
    }

    int* gi = g_idx + (b * NP + n) * KK;
    float* lc = out + LC_OFF;
#pragma unroll
    for (int k = 0; k < KK; k++) {
        int j = bi[k];
        gi[k] = j;
        float4 p = sp[j];
        lc[((b * 3 + 0) * NP + n) * KK + k] = q.x - p.x;   // center - neighbor
        lc[((b * 3 + 1) * NP + n) * KK + k] = q.y - p.y;
        lc[((b * 3 + 2) * NP + n) * KK + k] = q.z - p.z;
    }
}

// ---------------------------------------------------------------------------
// Kernel 2: pointwise MLP  F[point][co] = relu(bn2(w2 @ relu(bn1(w1 @ x))))
// grid 128 blocks (128 points each), block 256 = 16(tx:co) x 16(ty:p),
// each thread computes an 8co x 8p register tile (stride-16 blocking ->
// conflict-free LDS). Shared ~194.5 KB (needs dynamic smem attribute).
// ---------------------------------------------------------------------------
#define W1S   0
#define W2S   8192
#define XSO   24576
#define HSO   32768
#define HSTR  129
#define S1S   49280
#define T1S   49408
#define S2S   49536
#define T2S   49664
#define SM2_FLOATS 49792

__global__ void __launch_bounds__(256) mlp_kernel(
    const float* __restrict__ x,
    const float* __restrict__ w1, const float* __restrict__ g1,
    const float* __restrict__ b1, const float* __restrict__ m1,
    const float* __restrict__ v1,
    const float* __restrict__ w2, const float* __restrict__ g2,
    const float* __restrict__ b2, const float* __restrict__ m2,
    const float* __restrict__ v2)
{
    extern __shared__ float sm[];
    const int t = threadIdx.x;

    if (t < CO) {
        float i1 = g1[t] / sqrtf(v1[t] + 1e-5f);
        sm[S1S + t] = i1;
        sm[T1S + t] = fmaf(-m1[t], i1, b1[t]);
        float i2 = g2[t] / sqrtf(v2[t] + 1e-5f);
        sm[S2S + t] = i2;
        sm[T2S + t] = fmaf(-m2[t], i2, b2[t]);
    }
    // transposed weights: wT[c][co]
    for (int i = t; i < CI * CO; i += 256)
        sm[W1S + i] = w1[(i & 127) * CI + (i >> 7)];
    for (int i = t; i < CO * CO; i += 256)
        sm[W2S + i] = w2[(i & 127) * CO + (i >> 7)];

    const int b  = blockIdx.x >> 4;
    const int n0 = (blockIdx.x & 15) << 7;
    for (int i = t; i < CI * 128; i += 256) {
        int c = i >> 7, p = i & 127;
        sm[XSO + i] = x[(b * CI + c) * NP + n0 + p];
    }
    __syncthreads();

    const int tx = t & 15, ty = t >> 4;
    float acc[8][8];
#pragma unroll
    for (int u = 0; u < 8; u++)
#pragma unroll
        for (int v = 0; v < 8; v++) acc[u][v] = 0.f;

    // layer 1: 64 -> 128
    for (int c = 0; c < CI; c++) {
        float wv[8], xv[8];
#pragma unroll
        for (int u = 0; u < 8; u++) wv[u] = sm[W1S + c * 128 + tx + 16 * u];
#pragma unroll
        for (int v = 0; v < 8; v++) xv[v] = sm[XSO + c * 128 + ty + 16 * v];
#pragma unroll
        for (int u = 0; u < 8; u++)
#pragma unroll
            for (int v = 0; v < 8; v++)
                acc[u][v] = fmaf(wv[u], xv[v], acc[u][v]);
    }
    // bn1 + relu -> hs[c2][p]
#pragma unroll
    for (int u = 0; u < 8; u++) {
        int co = tx + 16 * u;
        float s = sm[S1S + co], o = sm[T1S + co];
#pragma unroll
        for (int v = 0; v < 8; v++) {
            float h = fmaxf(fmaf(acc[u][v], s, o), 0.f);
            sm[HSO + co * HSTR + ty + 16 * v] = h;
        }
    }
    __syncthreads();

#pragma unroll
    for (int u = 0; u < 8; u++)
#pragma unroll
        for (int v = 0; v < 8; v++) acc[u][v] = 0.f;

    // layer 2: 128 -> 128
    for (int c = 0; c < CO; c++) {
        float wv[8], hv[8];
#pragma unroll
        for (int u = 0; u < 8; u++) wv[u] = sm[W2S + c * 128 + tx + 16 * u];
#pragma unroll
        for (int v = 0; v < 8; v++) hv[v] = sm[HSO + c * HSTR + ty + 16 * v];
#pragma unroll
        for (int u = 0; u < 8; u++)
#pragma unroll
            for (int v = 0; v < 8; v++)
                acc[u][v] = fmaf(wv[u], hv[v], acc[u][v]);
    }
    // bn2 + relu -> F[point][co]
    const int gpb = blockIdx.x * 128;
#pragma unroll
    for (int u = 0; u < 8; u++) {
        int co = tx + 16 * u;
        float s = sm[S2S + co], o = sm[T2S + co];
#pragma unroll
        for (int v = 0; v < 8; v++) {
            int p = ty + 16 * v;
            g_F[(gpb + p) * CO + co] = fmaxf(fmaf(acc[u][v], s, o), 0.f);
        }
    }
}

// ---------------------------------------------------------------------------
// Kernel 3: gather F rows by idx -> knn_mlp_x, running max -> y.
// One block (128 threads = co) per (b,n). F reads are 512B-coalesced L2 hits;
// knn writes are 64B contiguous per thread (4x STG.128).
// ---------------------------------------------------------------------------
__global__ void __launch_bounds__(128) gather_kernel(float* __restrict__ out) {
    const int bn = blockIdx.x;             // 0 .. B*N-1
    const int b  = bn >> 11;
    const int n  = bn & (NP - 1);
    const int co = threadIdx.x;

    __shared__ int sidx[KK];
    if (co < KK) sidx[co] = g_idx[bn * KK + co];
    __syncthreads();

    const float* Fb = g_F + (b * NP) * CO + co;
    float v[KK];
    float mx = -3.402823466e38f;
#pragma unroll
    for (int k = 0; k < KK; k++) {
        float val = Fb[sidx[k] * CO];
        v[k] = val;
        mx = fmaxf(mx, val);
    }
    float4* kp = (float4*)(out + KNN_OFF + ((b * CO + co) * NP + n) * KK);
    kp[0] = make_float4(v[0],  v[1],  v[2],  v[3]);
    kp[1] = make_float4(v[4],  v[5],  v[6],  v[7]);
    kp[2] = make_float4(v[8],  v[9],  v[10], v[11]);
    kp[3] = make_float4(v[12], v[13], v[14], v[15]);
    out[(b * CO + co) * NP + n] = mx;
}

// ---------------------------------------------------------------------------
extern "C" void kernel_launch(void* const* d_in, const int* in_sizes, int n_in,
                              void* d_out, int out_size) {
    const float* x      = (const float*)d_in[0];
    const float* coords = (const float*)d_in[1];
    const float* w1     = (const float*)d_in[2];
    const float* g1     = (const float*)d_in[3];
    const float* b1     = (const float*)d_in[4];
    const float* m1     = (const float*)d_in[5];
    const float* v1     = (const float*)d_in[6];
    const float* w2     = (const float*)d_in[7];
    const float* g2     = (const float*)d_in[8];
    const float* b2     = (const float*)d_in[9];
    const float* m2     = (const float*)d_in[10];
    const float* v2     = (const float*)d_in[11];
    float* out = (float*)d_out;

    cudaFuncSetAttribute(mlp_kernel, cudaFuncAttributeMaxDynamicSharedMemorySize,
                         SM2_FLOATS * 4);

    knn_kernel<<<dim3(16, BB), 128>>>(coords, out);
    mlp_kernel<<<128, 256, SM2_FLOATS * 4>>>(x, w1, g1, b1, m1, v1,
                                             w2, g2, b2, m2, v2);
    gather_kernel<<<BB * NP, 128>>>(out);
}